// round 1
// baseline (speedup 1.0000x reference)
#include <cuda_runtime.h>

#define NB 8
#define NC 512
#define NT 1024
#define NHEADS 8
#define NCH 64
#define NGROUPS 32
#define NGC 16

// ---------------- scratch (alloc-free: __device__ globals) ----------------
__device__ float g_mu[NB * NGROUPS];
__device__ float g_rstd[NB * NGROUPS];
__device__ float g_qkv[(size_t)NB * 3 * NC * NT];   // 48 MB
__device__ float g_attn[(size_t)NB * NC * NT];      // 16 MB

// ---------------- GroupNorm statistics ----------------
// One block per (b, g). Group channels are contiguous: offset = bg * NGC * NT.
__global__ __launch_bounds__(256) void gn_stats_kernel(const float* __restrict__ x) {
    int bg = blockIdx.x;
    const float4* p4 = (const float4*)(x + (size_t)bg * NGC * NT);
    float s = 0.f, ss = 0.f;
    for (int i = threadIdx.x; i < NGC * NT / 4; i += 256) {
        float4 v = p4[i];
        s  += v.x + v.y + v.z + v.w;
        ss += v.x * v.x + v.y * v.y + v.z * v.z + v.w * v.w;
    }
    __shared__ float sh[512];
    sh[threadIdx.x] = s;
    sh[256 + threadIdx.x] = ss;
    __syncthreads();
    for (int off = 128; off > 0; off >>= 1) {
        if (threadIdx.x < off) {
            sh[threadIdx.x]       += sh[threadIdx.x + off];
            sh[256 + threadIdx.x] += sh[256 + threadIdx.x + off];
        }
        __syncthreads();
    }
    if (threadIdx.x == 0) {
        float inv = 1.f / (float)(NGC * NT);
        float mu  = sh[0] * inv;
        float var = sh[256] * inv - mu * mu;
        g_mu[bg] = mu;
        g_rstd[bg] = rsqrtf(var + 1e-5f);
    }
}

// ---------------- tiled SGEMM: Cout[b,m,n] = sum_k W[m,k] * Bsrc[b,k,n] + bias[m] ----------------
// 64x64 block tile, BK=16, 256 threads, 4x4 micro-tile.
// FUSE_NORM: B-operand is x normalized on the fly (GroupNorm affine).
// FUSE_RES : epilogue adds resid[b,m,n] (residual connection).
template <int M, bool FUSE_NORM, bool FUSE_RES>
__global__ __launch_bounds__(256) void gemm_kernel(
    const float* __restrict__ W, const float* __restrict__ Bsrc,
    const float* __restrict__ bias,
    const float* __restrict__ nw, const float* __restrict__ nb,
    const float* __restrict__ resid, float* __restrict__ Cout)
{
    __shared__ float As[16][68];  // [k][m]
    __shared__ float Bs[16][68];  // [k][n]
    int b  = blockIdx.z;
    int m0 = blockIdx.y << 6, n0 = blockIdx.x << 6;
    const float* Bb = Bsrc + (size_t)b * NC * NT;
    int tid = threadIdx.x;
    int tx = tid & 15, ty = tid >> 4;
    int arow = tid >> 2, acol = (tid & 3) << 2;   // A loader: one float4 along K
    int brow = tid >> 4, bcol = (tid & 15) << 2;  // B loader: one float4 along N
    float acc[4][4] = {};

    for (int k0 = 0; k0 < NC; k0 += 16) {
        float4 av = *(const float4*)(W + (size_t)(m0 + arow) * NC + k0 + acol);
        As[acol + 0][arow] = av.x;
        As[acol + 1][arow] = av.y;
        As[acol + 2][arow] = av.z;
        As[acol + 3][arow] = av.w;

        int kk = k0 + brow;
        float4 bv = *(const float4*)(Bb + (size_t)kk * NT + n0 + bcol);
        if (FUSE_NORM) {
            int g = kk >> 4;  // kk / NGC
            float rs = g_rstd[b * NGROUPS + g];
            float mu = g_mu[b * NGROUPS + g];
            float sw = nw[kk] * rs;
            float sb = nb[kk] - mu * sw;
            bv.x = bv.x * sw + sb;
            bv.y = bv.y * sw + sb;
            bv.z = bv.z * sw + sb;
            bv.w = bv.w * sw + sb;
        }
        *(float4*)&Bs[brow][bcol] = bv;
        __syncthreads();

        #pragma unroll
        for (int k = 0; k < 16; k++) {
            float a[4], bb2[4];
            *(float4*)a   = *(const float4*)&As[k][ty << 2];
            *(float4*)bb2 = *(const float4*)&Bs[k][tx << 2];
            #pragma unroll
            for (int i = 0; i < 4; i++)
                #pragma unroll
                for (int j = 0; j < 4; j++)
                    acc[i][j] += a[i] * bb2[j];
        }
        __syncthreads();
    }

    #pragma unroll
    for (int i = 0; i < 4; i++) {
        int m = m0 + (ty << 2) + i;
        float bv = bias[m];
        float4 o;
        o.x = acc[i][0] + bv;
        o.y = acc[i][1] + bv;
        o.z = acc[i][2] + bv;
        o.w = acc[i][3] + bv;
        if (FUSE_RES) {
            float4 r = *(const float4*)(resid + ((size_t)b * NC + m) * NT + n0 + (tx << 2));
            o.x += r.x; o.y += r.y; o.z += r.z; o.w += r.w;
        }
        *(float4*)(Cout + ((size_t)b * M + m) * NT + n0 + (tx << 2)) = o;
    }
}

// ---------------- flash attention ----------------
// grid: (T/64, B*HEADS). 64-query tiles, 64-key chunks, ch=64, online softmax.
// qkv layout: head h owns rows [h*192, h*192+192) of the 3C dim: q|k|v of 64 rows each.
__global__ __launch_bounds__(256) void attn_kernel() {
    extern __shared__ float sm[];
    float* Qs = sm;              // [64c][68] : q (pre-scaled by 1/8), later reused as [c][t] output stage
    float* Ks = sm + 4352;       // [64c][68]
    float* Vt = sm + 2 * 4352;   // [64s][68] : V transposed -> [s][c]
    float* Ps = sm + 3 * 4352;   // [64s][68] : P transposed -> [s][t]

    int qt0 = blockIdx.x << 6;
    int bh = blockIdx.y;
    int b = bh >> 3, h = bh & 7;
    const float* qp = g_qkv + ((size_t)b * 3 * NC + (size_t)h * 3 * NCH) * NT;
    const float* kp = qp + (size_t)NCH * NT;
    const float* vp = kp + (size_t)NCH * NT;

    int tid = threadIdx.x;
    int tx = tid & 15, ty = tid >> 4;

    // load Q tile [c][t], scale by ch^-0.5 = 1/8 (exact)
    for (int i = tid; i < 1024; i += 256) {
        int c = i >> 4, t4 = (i & 15) << 2;
        float4 q = *(const float4*)(qp + (size_t)c * NT + qt0 + t4);
        q.x *= 0.125f; q.y *= 0.125f; q.z *= 0.125f; q.w *= 0.125f;
        *(float4*)&Qs[c * 68 + t4] = q;
    }

    float m_i[4], l_i[4], acc[4][4] = {};
    #pragma unroll
    for (int i = 0; i < 4; i++) { m_i[i] = -1e30f; l_i[i] = 0.f; }

    for (int s0 = 0; s0 < NT; s0 += 64) {
        // load K [c][s] and V transposed [s][c]
        for (int i = tid; i < 1024; i += 256) {
            int c = i >> 4, s4 = (i & 15) << 2;
            *(float4*)&Ks[c * 68 + s4] = *(const float4*)(kp + (size_t)c * NT + s0 + s4);
            float4 v = *(const float4*)(vp + (size_t)c * NT + s0 + s4);
            Vt[(s4 + 0) * 68 + c] = v.x;
            Vt[(s4 + 1) * 68 + c] = v.y;
            Vt[(s4 + 2) * 68 + c] = v.z;
            Vt[(s4 + 3) * 68 + c] = v.w;
        }
        __syncthreads();

        // S[tq][s] = (Q/8)^T K ; thread tile: tq = ty*4+i, s = tx*4+j
        float sf[4][4] = {};
        #pragma unroll 8
        for (int c = 0; c < 64; c++) {
            float a[4], bb[4];
            *(float4*)a  = *(const float4*)&Qs[c * 68 + (ty << 2)];
            *(float4*)bb = *(const float4*)&Ks[c * 68 + (tx << 2)];
            #pragma unroll
            for (int i = 0; i < 4; i++)
                #pragma unroll
                for (int j = 0; j < 4; j++)
                    sf[i][j] += a[i] * bb[j];
        }

        // online softmax: rows span 16 tx-lanes (half-warp, width-16 shuffles)
        #pragma unroll
        for (int i = 0; i < 4; i++) {
            float mx = fmaxf(fmaxf(sf[i][0], sf[i][1]), fmaxf(sf[i][2], sf[i][3]));
            #pragma unroll
            for (int off = 8; off > 0; off >>= 1)
                mx = fmaxf(mx, __shfl_xor_sync(0xffffffffu, mx, off, 16));
            float nm = fmaxf(m_i[i], mx);
            float corr = __expf(m_i[i] - nm);
            m_i[i] = nm;
            float rs = 0.f;
            #pragma unroll
            for (int j = 0; j < 4; j++) {
                float p = __expf(sf[i][j] - nm);
                sf[i][j] = p;
                rs += p;
            }
            #pragma unroll
            for (int off = 8; off > 0; off >>= 1)
                rs += __shfl_xor_sync(0xffffffffu, rs, off, 16);
            l_i[i] = l_i[i] * corr + rs;
            #pragma unroll
            for (int j = 0; j < 4; j++) acc[i][j] *= corr;
        }

        // P transposed into smem: Ps[s][t]
        #pragma unroll
        for (int i = 0; i < 4; i++)
            #pragma unroll
            for (int j = 0; j < 4; j++)
                Ps[((tx << 2) + j) * 68 + (ty << 2) + i] = sf[i][j];
        __syncthreads();

        // O[tq][c] += P[tq][s] * V[c][s] ; thread tile: tq = ty*4+i, c = tx*4+j
        #pragma unroll 8
        for (int s = 0; s < 64; s++) {
            float p[4], vv[4];
            *(float4*)p  = *(const float4*)&Ps[s * 68 + (ty << 2)];
            *(float4*)vv = *(const float4*)&Vt[s * 68 + (tx << 2)];
            #pragma unroll
            for (int i = 0; i < 4; i++)
                #pragma unroll
                for (int j = 0; j < 4; j++)
                    acc[i][j] += p[i] * vv[j];
        }
        __syncthreads();
    }

    // normalize and stage as [c][t] in Qs, then coalesced store
    #pragma unroll
    for (int i = 0; i < 4; i++) {
        float inv = 1.f / l_i[i];
        #pragma unroll
        for (int j = 0; j < 4; j++)
            Qs[((tx << 2) + j) * 68 + (ty << 2) + i] = acc[i][j] * inv;
    }
    __syncthreads();
    float* outp = g_attn + ((size_t)b * NC + (size_t)h * NCH) * NT;
    for (int i = tid; i < 1024; i += 256) {
        int c = i >> 4, t4 = (i & 15) << 2;
        *(float4*)(outp + (size_t)c * NT + qt0 + t4) = *(const float4*)&Qs[c * 68 + t4];
    }
}

// ---------------- launch ----------------
extern "C" void kernel_launch(void* const* d_in, const int* in_sizes, int n_in,
                              void* d_out, int out_size) {
    const float* x      = (const float*)d_in[0];
    const float* norm_w = (const float*)d_in[1];
    const float* norm_b = (const float*)d_in[2];
    const float* qkv_w  = (const float*)d_in[3];
    const float* qkv_b  = (const float*)d_in[4];
    const float* proj_w = (const float*)d_in[5];
    const float* proj_b = (const float*)d_in[6];
    float* out = (float*)d_out;

    float *qkv_ptr = 0, *attn_ptr = 0;
    cudaGetSymbolAddress((void**)&qkv_ptr, g_qkv);
    cudaGetSymbolAddress((void**)&attn_ptr, g_attn);

    const int attn_smem = 4 * 4352 * 4;  // 69632 B
    cudaFuncSetAttribute(attn_kernel, cudaFuncAttributeMaxDynamicSharedMemorySize, attn_smem);

    gn_stats_kernel<<<NB * NGROUPS, 256>>>(x);

    dim3 gq(NT / 64, (3 * NC) / 64, NB);
    gemm_kernel<3 * NC, true, false><<<gq, 256>>>(qkv_w, x, qkv_b, norm_w, norm_b, nullptr, qkv_ptr);

    dim3 ga(NT / 64, NB * NHEADS);
    attn_kernel<<<ga, 256, attn_smem>>>();

    dim3 gp(NT / 64, NC / 64, NB);
    gemm_kernel<NC, false, true><<<gp, 256>>>(proj_w, attn_ptr, proj_b, nullptr, nullptr, x, out);
}

// round 3
// speedup vs baseline: 2.2402x; 2.2402x over previous
#include <cuda_runtime.h>
#include <cstdint>

#define NB 8
#define NC 512
#define NT 1024
#define NHEADS 8
#define NCH 64
#define NGROUPS 32
#define NGC 16

// ---------------- scratch (alloc-free: __device__ globals) ----------------
__device__ float g_mu[NB * NGROUPS];
__device__ float g_rstd[NB * NGROUPS];
__device__ float g_qkv[(size_t)NB * 3 * NC * NT];   // 48 MB
__device__ float g_attn[(size_t)NB * NC * NT];      // 16 MB

// ---------------- helpers ----------------
__device__ __forceinline__ uint32_t f2tf32(float f) {
    uint32_t r;
    asm("cvt.rna.tf32.f32 %0, %1;" : "=r"(r) : "f"(f));
    return r;
}
// D += A*B, m16n8k8 TF32. d: 4 floats, a: 4 b32, b: 2 b32.
__device__ __forceinline__ void mma_tf32(float* d, const uint32_t* a, const uint32_t* b) {
    asm volatile(
        "mma.sync.aligned.m16n8k8.row.col.f32.tf32.tf32.f32 "
        "{%0,%1,%2,%3}, {%4,%5,%6,%7}, {%8,%9}, {%0,%1,%2,%3};"
        : "+f"(d[0]), "+f"(d[1]), "+f"(d[2]), "+f"(d[3])
        : "r"(a[0]), "r"(a[1]), "r"(a[2]), "r"(a[3]), "r"(b[0]), "r"(b[1]));
}

// ---------------- GroupNorm statistics ----------------
__global__ __launch_bounds__(256) void gn_stats_kernel(const float* __restrict__ x) {
    int bg = blockIdx.x;
    const float4* p4 = (const float4*)(x + (size_t)bg * NGC * NT);
    float s = 0.f, ss = 0.f;
    for (int i = threadIdx.x; i < NGC * NT / 4; i += 256) {
        float4 v = p4[i];
        s  += v.x + v.y + v.z + v.w;
        ss += v.x * v.x + v.y * v.y + v.z * v.z + v.w * v.w;
    }
    __shared__ float sh[512];
    sh[threadIdx.x] = s;
    sh[256 + threadIdx.x] = ss;
    __syncthreads();
    for (int off = 128; off > 0; off >>= 1) {
        if (threadIdx.x < off) {
            sh[threadIdx.x]       += sh[threadIdx.x + off];
            sh[256 + threadIdx.x] += sh[256 + threadIdx.x + off];
        }
        __syncthreads();
    }
    if (threadIdx.x == 0) {
        float inv = 1.f / (float)(NGC * NT);
        float mu  = sh[0] * inv;
        float var = sh[256] * inv - mu * mu;
        g_mu[bg] = mu;
        g_rstd[bg] = rsqrtf(var + 1e-5f);
    }
}

// ---------------- TF32 mma.sync GEMM ----------------
// Cout[b,m,n] = sum_k W[m,k]*Bsrc[b,k,n] + bias[m] (+resid).
// Block tile 128x128, BK=32, 8 warps (2x4), warptile 64x32, m16n8k8 frags.
// smem: A [128][36] (bank stride 4 -> conflict-free A-frags),
//       B [32][136] (bank stride 8 -> conflict-free B-frags). Double buffered.
template <int MTOT, bool FUSE_NORM, bool FUSE_RES>
__global__ __launch_bounds__(256) void mma_gemm_kernel(
    const float* __restrict__ W, const float* __restrict__ Bsrc,
    const float* __restrict__ bias,
    const float* __restrict__ nw, const float* __restrict__ nb,
    const float* __restrict__ resid, float* __restrict__ Cout)
{
    extern __shared__ uint32_t smu[];
    uint32_t* const Ab[2] = { smu, smu + 4608 };           // 128*36
    uint32_t* const Bbuf[2] = { smu + 9216, smu + 13568 }; // 32*136
    const int b = blockIdx.z, m0 = blockIdx.y << 7, n0 = blockIdx.x << 7;
    const float* Bb = Bsrc + (size_t)b * NC * NT;
    const int tid = threadIdx.x, lane = tid & 31, warp = tid >> 5;
    const int wm = warp >> 2, wn = warp & 3;
    const int qr = lane >> 2, qc = lane & 3;

    float acc[4][4][4] = {};
    float4 ra[4], rb[4];

    // global loaders (regs) -----------------------------------------------
    auto LOADA = [&](int k0) {
        #pragma unroll
        for (int r = 0; r < 4; r++) {
            int idx = tid + (r << 8);
            int row = idx >> 3, k4 = (idx & 7) << 2;
            ra[r] = *(const float4*)(W + (size_t)(m0 + row) * NC + k0 + k4);
        }
    };
    auto LOADB = [&](int k0) {
        #pragma unroll
        for (int r = 0; r < 4; r++) {
            int idx = tid + (r << 8);
            int k = idx >> 5, n4 = (idx & 31) << 2;
            float4 v = *(const float4*)(Bb + (size_t)(k0 + k) * NT + n0 + n4);
            if (FUSE_NORM) {
                int kk = k0 + k, g = kk >> 4;
                float rs = g_rstd[b * NGROUPS + g];
                float mu = g_mu[b * NGROUPS + g];
                float sw = nw[kk] * rs, sb = nb[kk] - mu * sw;
                v.x = v.x * sw + sb; v.y = v.y * sw + sb;
                v.z = v.z * sw + sb; v.w = v.w * sw + sb;
            }
            rb[r] = v;
        }
    };
    auto STORE = [&](int buf) {
        #pragma unroll
        for (int r = 0; r < 4; r++) {
            int idx = tid + (r << 8);
            int row = idx >> 3, k4 = (idx & 7) << 2;
            uint32_t* p = Ab[buf] + row * 36 + k4;
            p[0] = f2tf32(ra[r].x); p[1] = f2tf32(ra[r].y);
            p[2] = f2tf32(ra[r].z); p[3] = f2tf32(ra[r].w);
            int k = idx >> 5, n4 = (idx & 31) << 2;
            uint32_t* q = Bbuf[buf] + k * 136 + n4;
            q[0] = f2tf32(rb[r].x); q[1] = f2tf32(rb[r].y);
            q[2] = f2tf32(rb[r].z); q[3] = f2tf32(rb[r].w);
        }
    };

    LOADA(0); LOADB(0); STORE(0);
    __syncthreads();

    #pragma unroll 1
    for (int it = 0; it < 16; it++) {
        const int cur = it & 1;
        if (it < 15) { LOADA((it + 1) << 5); LOADB((it + 1) << 5); }
        const uint32_t* A = Ab[cur];
        const uint32_t* Bs = Bbuf[cur];
        #pragma unroll
        for (int ks = 0; ks < 4; ks++) {
            uint32_t af[4][4], bf[4][2];
            #pragma unroll
            for (int mf = 0; mf < 4; mf++) {
                int r = wm * 64 + mf * 16 + qr, c = ks * 8 + qc;
                af[mf][0] = A[r * 36 + c];
                af[mf][1] = A[(r + 8) * 36 + c];
                af[mf][2] = A[r * 36 + c + 4];
                af[mf][3] = A[(r + 8) * 36 + c + 4];
            }
            #pragma unroll
            for (int nf = 0; nf < 4; nf++) {
                int n = wn * 32 + nf * 8 + qr, k = ks * 8 + qc;
                bf[nf][0] = Bs[k * 136 + n];
                bf[nf][1] = Bs[(k + 4) * 136 + n];
            }
            #pragma unroll
            for (int mf = 0; mf < 4; mf++)
                #pragma unroll
                for (int nf = 0; nf < 4; nf++)
                    mma_tf32(acc[mf][nf], af[mf], bf[nf]);
        }
        if (it < 15) STORE((it + 1) & 1);
        __syncthreads();
    }

    // epilogue: C-frag layout, float2 stores -------------------------------
    #pragma unroll
    for (int mf = 0; mf < 4; mf++) {
        int m_r = m0 + wm * 64 + mf * 16 + qr;
        float bv0 = bias[m_r], bv1 = bias[m_r + 8];
        #pragma unroll
        for (int nf = 0; nf < 4; nf++) {
            int n = n0 + wn * 32 + nf * 8 + 2 * qc;
            float2 v0 = { acc[mf][nf][0] + bv0, acc[mf][nf][1] + bv0 };
            float2 v1 = { acc[mf][nf][2] + bv1, acc[mf][nf][3] + bv1 };
            if (FUSE_RES) {
                float2 r0 = *(const float2*)(resid + ((size_t)b * NC + m_r) * NT + n);
                float2 r1 = *(const float2*)(resid + ((size_t)b * NC + m_r + 8) * NT + n);
                v0.x += r0.x; v0.y += r0.y;
                v1.x += r1.x; v1.y += r1.y;
            }
            *(float2*)(Cout + ((size_t)b * MTOT + m_r) * NT + n) = v0;
            *(float2*)(Cout + ((size_t)b * MTOT + m_r + 8) * NT + n) = v1;
        }
    }
}

// ---------------- flash attention with mma.sync TF32 ----------------
// 128 threads (4 warps). Block: 64 queries x full T. Warp w: 16 q rows.
// All tiles in natural [channel][token] stride-68 smem layout (no transposes).
__global__ __launch_bounds__(128) void attn_kernel() {
    extern __shared__ uint32_t smw[];
    uint32_t* const Qs = smw;              // [64 c][68] (tf32)
    uint32_t* const Ks = smw + 4352;       // [64 c][68]
    uint32_t* const Vs = smw + 2 * 4352;   // [64 c][68]
    uint32_t* const Ps = smw + 3 * 4352;   // [64 q][68] (tf32 P)

    const int qt0 = blockIdx.x << 6;
    const int bh = blockIdx.y;
    const int b = bh >> 3, h = bh & 7;
    const float* qp = g_qkv + ((size_t)b * 3 * NC + (size_t)h * 3 * NCH) * NT;
    const float* kp = qp + (size_t)NCH * NT;
    const float* vp = kp + (size_t)NCH * NT;

    const int tid = threadIdx.x, lane = tid & 31, w = tid >> 5;
    const int qr = lane >> 2, qc = lane & 3;
    const int q0 = w << 4;  // warp's q-row base within tile

    // load Q (scale 1/8, tf32) into Qs[c][t]
    #pragma unroll
    for (int r = 0; r < 8; r++) {
        int idx = tid + (r << 7);
        int c = idx >> 4, t4 = (idx & 15) << 2;
        float4 v = *(const float4*)(qp + (size_t)c * NT + qt0 + t4);
        uint32_t* p = Qs + c * 68 + t4;
        p[0] = f2tf32(v.x * 0.125f); p[1] = f2tf32(v.y * 0.125f);
        p[2] = f2tf32(v.z * 0.125f); p[3] = f2tf32(v.w * 0.125f);
    }

    float m_i[2] = { -1e30f, -1e30f };
    float l_i[2] = { 0.f, 0.f };
    float o[8][4] = {};

    for (int s0 = 0; s0 < NT; s0 += 64) {
        __syncthreads();  // protect prior K/V reads (first iter: Q stores)
        #pragma unroll
        for (int r = 0; r < 8; r++) {
            int idx = tid + (r << 7);
            int c = idx >> 4, s4 = (idx & 15) << 2;
            float4 kv = *(const float4*)(kp + (size_t)c * NT + s0 + s4);
            float4 vv = *(const float4*)(vp + (size_t)c * NT + s0 + s4);
            uint32_t* pk = Ks + c * 68 + s4;
            pk[0] = f2tf32(kv.x); pk[1] = f2tf32(kv.y);
            pk[2] = f2tf32(kv.z); pk[3] = f2tf32(kv.w);
            uint32_t* pv = Vs + c * 68 + s4;
            pv[0] = f2tf32(vv.x); pv[1] = f2tf32(vv.y);
            pv[2] = f2tf32(vv.z); pv[3] = f2tf32(vv.w);
        }
        __syncthreads();

        // ---- S = (Q/8)^T K : warp computes 16q x 64s, sf C-frags ----
        float sf[8][4] = {};
        #pragma unroll
        for (int ks = 0; ks < 8; ks++) {
            uint32_t a[4];
            int c = ks * 8 + qc;
            a[0] = Qs[c * 68 + q0 + qr];
            a[1] = Qs[c * 68 + q0 + qr + 8];
            a[2] = Qs[(c + 4) * 68 + q0 + qr];
            a[3] = Qs[(c + 4) * 68 + q0 + qr + 8];
            #pragma unroll
            for (int nf = 0; nf < 8; nf++) {
                uint32_t bb[2];
                int s = nf * 8 + qr;
                bb[0] = Ks[c * 68 + s];
                bb[1] = Ks[(c + 4) * 68 + s];
                mma_tf32(sf[nf], a, bb);
            }
        }

        // ---- online softmax (rows qr / qr+8, quad shuffles) ----
        float mx0 = -1e30f, mx1 = -1e30f;
        #pragma unroll
        for (int nf = 0; nf < 8; nf++) {
            mx0 = fmaxf(mx0, fmaxf(sf[nf][0], sf[nf][1]));
            mx1 = fmaxf(mx1, fmaxf(sf[nf][2], sf[nf][3]));
        }
        #pragma unroll
        for (int off = 1; off <= 2; off <<= 1) {
            mx0 = fmaxf(mx0, __shfl_xor_sync(0xffffffffu, mx0, off));
            mx1 = fmaxf(mx1, __shfl_xor_sync(0xffffffffu, mx1, off));
        }
        float nm0 = fmaxf(m_i[0], mx0), nm1 = fmaxf(m_i[1], mx1);
        float corr0 = __expf(m_i[0] - nm0), corr1 = __expf(m_i[1] - nm1);
        m_i[0] = nm0; m_i[1] = nm1;
        float sum0 = 0.f, sum1 = 0.f;
        #pragma unroll
        for (int nf = 0; nf < 8; nf++) {
            sf[nf][0] = __expf(sf[nf][0] - nm0);
            sf[nf][1] = __expf(sf[nf][1] - nm0);
            sf[nf][2] = __expf(sf[nf][2] - nm1);
            sf[nf][3] = __expf(sf[nf][3] - nm1);
            sum0 += sf[nf][0] + sf[nf][1];
            sum1 += sf[nf][2] + sf[nf][3];
        }
        #pragma unroll
        for (int off = 1; off <= 2; off <<= 1) {
            sum0 += __shfl_xor_sync(0xffffffffu, sum0, off);
            sum1 += __shfl_xor_sync(0xffffffffu, sum1, off);
        }
        l_i[0] = l_i[0] * corr0 + sum0;
        l_i[1] = l_i[1] * corr1 + sum1;
        #pragma unroll
        for (int nf = 0; nf < 8; nf++) {
            o[nf][0] *= corr0; o[nf][1] *= corr0;
            o[nf][2] *= corr1; o[nf][3] *= corr1;
        }

        // ---- P -> warp-private smem rows [q0, q0+16) ----
        #pragma unroll
        for (int nf = 0; nf < 8; nf++) {
            int sc = nf * 8 + 2 * qc;
            Ps[(q0 + qr) * 68 + sc]     = f2tf32(sf[nf][0]);
            Ps[(q0 + qr) * 68 + sc + 1] = f2tf32(sf[nf][1]);
            Ps[(q0 + qr + 8) * 68 + sc]     = f2tf32(sf[nf][2]);
            Ps[(q0 + qr + 8) * 68 + sc + 1] = f2tf32(sf[nf][3]);
        }
        __syncwarp();

        // ---- O += P V^T : A = P[q][s], B from Vs[c][s] ----
        #pragma unroll
        for (int ks = 0; ks < 8; ks++) {
            uint32_t a[4];
            int s = ks * 8 + qc;
            a[0] = Ps[(q0 + qr) * 68 + s];
            a[1] = Ps[(q0 + qr + 8) * 68 + s];
            a[2] = Ps[(q0 + qr) * 68 + s + 4];
            a[3] = Ps[(q0 + qr + 8) * 68 + s + 4];
            #pragma unroll
            for (int nf = 0; nf < 8; nf++) {
                uint32_t bb[2];
                int c = nf * 8 + qr;
                bb[0] = Vs[c * 68 + s];
                bb[1] = Vs[c * 68 + s + 4];
                mma_tf32(o[nf], a, bb);
            }
        }
    }

    // ---- epilogue: normalize, stage [c][t] in Qs, coalesced store ----
    float inv0 = 1.f / l_i[0], inv1 = 1.f / l_i[1];
    __syncthreads();  // all warps done reading Qs
    float* Os = (float*)Qs;
    #pragma unroll
    for (int nf = 0; nf < 8; nf++) {
        int c = nf * 8 + 2 * qc;
        Os[c * 68 + q0 + qr]           = o[nf][0] * inv0;
        Os[(c + 1) * 68 + q0 + qr]     = o[nf][1] * inv0;
        Os[c * 68 + q0 + qr + 8]       = o[nf][2] * inv1;
        Os[(c + 1) * 68 + q0 + qr + 8] = o[nf][3] * inv1;
    }
    __syncthreads();
    float* outp = g_attn + ((size_t)b * NC + (size_t)h * NCH) * NT;
    #pragma unroll
    for (int r = 0; r < 8; r++) {
        int idx = tid + (r << 7);
        int c = idx >> 4, t4 = (idx & 15) << 2;
        *(float4*)(outp + (size_t)c * NT + qt0 + t4) = *(const float4*)&Os[c * 68 + t4];
    }
}

// ---------------- launch ----------------
extern "C" void kernel_launch(void* const* d_in, const int* in_sizes, int n_in,
                              void* d_out, int out_size) {
    const float* x      = (const float*)d_in[0];
    const float* norm_w = (const float*)d_in[1];
    const float* norm_b = (const float*)d_in[2];
    const float* qkv_w  = (const float*)d_in[3];
    const float* qkv_b  = (const float*)d_in[4];
    const float* proj_w = (const float*)d_in[5];
    const float* proj_b = (const float*)d_in[6];
    float* out = (float*)d_out;

    float *qkv_ptr = 0, *attn_ptr = 0;
    cudaGetSymbolAddress((void**)&qkv_ptr, g_qkv);
    cudaGetSymbolAddress((void**)&attn_ptr, g_attn);

    const int gemm_smem = (2 * 4608 + 2 * 4352) * 4;  // 71680
    cudaFuncSetAttribute(mma_gemm_kernel<3 * NC, true, false>,
                         cudaFuncAttributeMaxDynamicSharedMemorySize, gemm_smem);
    cudaFuncSetAttribute(mma_gemm_kernel<NC, false, true>,
                         cudaFuncAttributeMaxDynamicSharedMemorySize, gemm_smem);
    const int attn_smem = 4 * 4352 * 4;  // 69632
    cudaFuncSetAttribute(attn_kernel, cudaFuncAttributeMaxDynamicSharedMemorySize, attn_smem);

    gn_stats_kernel<<<NB * NGROUPS, 256>>>(x);

    dim3 gq(NT / 128, (3 * NC) / 128, NB);
    mma_gemm_kernel<3 * NC, true, false><<<gq, 256, gemm_smem>>>(
        qkv_w, x, qkv_b, norm_w, norm_b, nullptr, qkv_ptr);

    dim3 ga(NT / 64, NB * NHEADS);
    attn_kernel<<<ga, 128, attn_smem>>>();

    dim3 gp(NT / 128, NC / 128, NB);
    mma_gemm_kernel<NC, false, true><<<gp, 256, gemm_smem>>>(
        proj_w, attn_ptr, proj_b, nullptr, nullptr, x, out);
}

// round 4
// speedup vs baseline: 2.8351x; 1.2655x over previous
#include <cuda_runtime.h>
#include <cstdint>

#define NB 8
#define NC 512
#define NT 1024
#define NHEADS 8
#define NCH 64
#define NGROUPS 32
#define NGC 16

// ---------------- scratch (alloc-free: __device__ globals) ----------------
__device__ float g_mu[NB * NGROUPS];
__device__ float g_rstd[NB * NGROUPS];
__device__ float g_xn[(size_t)NB * NC * NT];        // 16 MB, tf32 bits
__device__ float g_wq[(size_t)3 * NC * NC];         // 3 MB,  tf32 bits
__device__ float g_wp[(size_t)NC * NC];             // 1 MB,  tf32 bits
__device__ float g_qkv[(size_t)NB * 3 * NC * NT];   // 48 MB, tf32 bits
__device__ float g_attn[(size_t)NB * NC * NT];      // 16 MB, tf32 bits

// ---------------- helpers ----------------
__device__ __forceinline__ uint32_t f2tf32(float f) {
    uint32_t r;
    asm("cvt.rna.tf32.f32 %0, %1;" : "=r"(r) : "f"(f));
    return r;
}
__device__ __forceinline__ float tf32f(float f) { return __uint_as_float(f2tf32(f)); }
__device__ __forceinline__ void mma_tf32(float* d, const uint32_t* a, const uint32_t* b) {
    asm volatile(
        "mma.sync.aligned.m16n8k8.row.col.f32.tf32.tf32.f32 "
        "{%0,%1,%2,%3}, {%4,%5,%6,%7}, {%8,%9}, {%0,%1,%2,%3};"
        : "+f"(d[0]), "+f"(d[1]), "+f"(d[2]), "+f"(d[3])
        : "r"(a[0]), "r"(a[1]), "r"(a[2]), "r"(a[3]), "r"(b[0]), "r"(b[1]));
}
__device__ __forceinline__ void cp16(uint32_t dst, const void* src) {
    asm volatile("cp.async.cg.shared.global [%0], [%1], 16;" :: "r"(dst), "l"(src));
}
__device__ __forceinline__ void cp_commit() {
    asm volatile("cp.async.commit_group;" ::: "memory");
}
template <int N>
__device__ __forceinline__ void cp_wait() {
    asm volatile("cp.async.wait_group %0;" :: "n"(N) : "memory");
}

// ---------------- weight pre-convert (fp32 -> tf32 bits) ----------------
__global__ __launch_bounds__(256) void conv_kernel(const float* __restrict__ in,
                                                   float* __restrict__ out, int n4) {
    int i = blockIdx.x * 256 + threadIdx.x;
    if (i < n4) {
        float4 v = ((const float4*)in)[i];
        v.x = tf32f(v.x); v.y = tf32f(v.y); v.z = tf32f(v.z); v.w = tf32f(v.w);
        ((float4*)out)[i] = v;
    }
}

// ---------------- GroupNorm: stats + apply + tf32 convert ----------------
__global__ __launch_bounds__(256) void gn_kernel(const float* __restrict__ x,
                                                 const float* __restrict__ nw,
                                                 const float* __restrict__ nb) {
    int bg = blockIdx.x;
    int g = bg & (NGROUPS - 1);
    const float4* p4 = (const float4*)(x + (size_t)bg * NGC * NT);
    float4* o4 = (float4*)(g_xn + (size_t)bg * NGC * NT);
    float s = 0.f, ss = 0.f;
    for (int i = threadIdx.x; i < NGC * NT / 4; i += 256) {
        float4 v = p4[i];
        s  += v.x + v.y + v.z + v.w;
        ss += v.x * v.x + v.y * v.y + v.z * v.z + v.w * v.w;
    }
    __shared__ float sh[512];
    sh[threadIdx.x] = s;
    sh[256 + threadIdx.x] = ss;
    __syncthreads();
    for (int off = 128; off > 0; off >>= 1) {
        if (threadIdx.x < off) {
            sh[threadIdx.x]       += sh[threadIdx.x + off];
            sh[256 + threadIdx.x] += sh[256 + threadIdx.x + off];
        }
        __syncthreads();
    }
    float inv = 1.f / (float)(NGC * NT);
    float mu  = sh[0] * inv;
    float var = sh[256] * inv - mu * mu;
    float rs = rsqrtf(var + 1e-5f);
    for (int i = threadIdx.x; i < NGC * NT / 4; i += 256) {
        int c = g * NGC + (i >> 8);  // 256 float4 per channel row
        float sw = nw[c] * rs, sb = nb[c] - mu * sw;
        float4 v = p4[i];
        v.x = tf32f(v.x * sw + sb); v.y = tf32f(v.y * sw + sb);
        v.z = tf32f(v.z * sw + sb); v.w = tf32f(v.w * sw + sb);
        o4[i] = v;
    }
}

// ---------------- TF32 mma.sync GEMM, 3-stage cp.async pipeline ----------------
// Cout[b,m,n] = sum_k W[m,k]*Bsrc[b,k,n] + bias[m] (+resid).
// A,B already tf32 bits. Block 128x128, BK=32, 8 warps, warptile 64x32.
// smem/stage: A[128][36] + B[32][136].
template <int MTOT, bool OUT_TF32, bool FUSE_RES>
__global__ __launch_bounds__(256, 2) void mma_gemm_kernel(
    const float* __restrict__ W, const float* __restrict__ Bsrc,
    const float* __restrict__ bias,
    const float* __restrict__ resid, float* __restrict__ Cout)
{
    extern __shared__ uint32_t smu[];
    const uint32_t sbase = (uint32_t)__cvta_generic_to_shared(smu);
    const int b = blockIdx.z, m0 = blockIdx.y << 7, n0 = blockIdx.x << 7;
    const float* Bb = Bsrc + (size_t)b * NC * NT;
    const int tid = threadIdx.x, lane = tid & 31, warp = tid >> 5;
    const int wm = warp >> 2, wn = warp & 3;
    const int qr = lane >> 2, qc = lane & 3;

    // per-stage word offsets: stage s at s*8960 (A 4608 + B 4352)
    auto ISSUE = [&](int stage, int k0) {
        uint32_t abase = sbase + (uint32_t)stage * 8960u * 4u;
        uint32_t bbase = abase + 4608u * 4u;
        #pragma unroll
        for (int r = 0; r < 4; r++) {
            int idx = tid + (r << 8);
            int row = idx >> 3, c4 = (idx & 7) << 2;
            cp16(abase + ((uint32_t)row * 36u + c4) * 4u,
                 W + (size_t)(m0 + row) * NC + k0 + c4);
            int k = idx >> 5, n4 = (idx & 31) << 2;
            cp16(bbase + ((uint32_t)k * 136u + n4) * 4u,
                 Bb + (size_t)(k0 + k) * NT + n0 + n4);
        }
    };

    float acc[4][4][4] = {};

    ISSUE(0, 0); cp_commit();
    ISSUE(1, 32); cp_commit();

    #pragma unroll 1
    for (int it = 0; it < 16; it++) {
        cp_wait<1>();
        __syncthreads();
        if (it + 2 < 16) ISSUE((it + 2) % 3, (it + 2) << 5);
        cp_commit();

        const uint32_t* A  = smu + (it % 3) * 8960;
        const uint32_t* Bs = A + 4608;
        #pragma unroll
        for (int ks = 0; ks < 4; ks++) {
            uint32_t af[4][4], bf[4][2];
            #pragma unroll
            for (int mf = 0; mf < 4; mf++) {
                int r = wm * 64 + mf * 16 + qr, c = ks * 8 + qc;
                af[mf][0] = A[r * 36 + c];
                af[mf][1] = A[(r + 8) * 36 + c];
                af[mf][2] = A[r * 36 + c + 4];
                af[mf][3] = A[(r + 8) * 36 + c + 4];
            }
            #pragma unroll
            for (int nf = 0; nf < 4; nf++) {
                int n = wn * 32 + nf * 8 + qr, k = ks * 8 + qc;
                bf[nf][0] = Bs[k * 136 + n];
                bf[nf][1] = Bs[(k + 4) * 136 + n];
            }
            #pragma unroll
            for (int mf = 0; mf < 4; mf++)
                #pragma unroll
                for (int nf = 0; nf < 4; nf++)
                    mma_tf32(acc[mf][nf], af[mf], bf[nf]);
        }
    }

    // epilogue
    #pragma unroll
    for (int mf = 0; mf < 4; mf++) {
        int m_r = m0 + wm * 64 + mf * 16 + qr;
        float bv0 = bias[m_r], bv1 = bias[m_r + 8];
        #pragma unroll
        for (int nf = 0; nf < 4; nf++) {
            int n = n0 + wn * 32 + nf * 8 + 2 * qc;
            float2 v0 = { acc[mf][nf][0] + bv0, acc[mf][nf][1] + bv0 };
            float2 v1 = { acc[mf][nf][2] + bv1, acc[mf][nf][3] + bv1 };
            if (FUSE_RES) {
                float2 r0 = *(const float2*)(resid + ((size_t)b * NC + m_r) * NT + n);
                float2 r1 = *(const float2*)(resid + ((size_t)b * NC + m_r + 8) * NT + n);
                v0.x += r0.x; v0.y += r0.y;
                v1.x += r1.x; v1.y += r1.y;
            }
            if (OUT_TF32) {
                v0.x = tf32f(v0.x); v0.y = tf32f(v0.y);
                v1.x = tf32f(v1.x); v1.y = tf32f(v1.y);
            }
            *(float2*)(Cout + ((size_t)b * MTOT + m_r) * NT + n) = v0;
            *(float2*)(Cout + ((size_t)b * MTOT + m_r + 8) * NT + n) = v1;
        }
    }
}

// ---------------- flash attention, cp.async double-buffered K/V ----------------
// 128 threads (4 warps), 64-query tile, 64-key chunks, tf32 inputs from g_qkv.
// QK scale (1/8) applied post-mma on S.
__global__ __launch_bounds__(128, 2) void attn_kernel() {
    extern __shared__ uint32_t smw[];
    const uint32_t sbase = (uint32_t)__cvta_generic_to_shared(smw);
    uint32_t* const Qs = smw;                          // [64c][68]
    uint32_t* const Ks[2] = { smw + 4352, smw + 2 * 4352 };
    uint32_t* const Vs[2] = { smw + 3 * 4352, smw + 4 * 4352 };
    uint32_t* const Ps = smw + 5 * 4352;               // [64q][68]

    const int qt0 = blockIdx.x << 6;
    const int bh = blockIdx.y;
    const int b = bh >> 3, h = bh & 7;
    const float* qp = g_qkv + ((size_t)b * 3 * NC + (size_t)h * 3 * NCH) * NT;
    const float* kp = qp + (size_t)NCH * NT;
    const float* vp = kp + (size_t)NCH * NT;

    const int tid = threadIdx.x, lane = tid & 31, w = tid >> 5;
    const int qr = lane >> 2, qc = lane & 3;
    const int q0 = w << 4;

    auto ISSUE_KV = [&](int buf, int s0) {
        uint32_t kb = sbase + (1u + (uint32_t)buf) * 4352u * 4u;
        uint32_t vb = sbase + (3u + (uint32_t)buf) * 4352u * 4u;
        #pragma unroll
        for (int r = 0; r < 8; r++) {
            int idx = tid + (r << 7);
            int c = idx >> 4, s4 = (idx & 15) << 2;
            uint32_t off = ((uint32_t)c * 68u + s4) * 4u;
            cp16(kb + off, kp + (size_t)c * NT + s0 + s4);
            cp16(vb + off, vp + (size_t)c * NT + s0 + s4);
        }
    };

    // prologue: Q + chunk0 (group0), chunk1 (group1)
    #pragma unroll
    for (int r = 0; r < 8; r++) {
        int idx = tid + (r << 7);
        int c = idx >> 4, t4 = (idx & 15) << 2;
        cp16(sbase + ((uint32_t)c * 68u + t4) * 4u, qp + (size_t)c * NT + qt0 + t4);
    }
    ISSUE_KV(0, 0); cp_commit();
    ISSUE_KV(1, 64); cp_commit();

    float m_i[2] = { -1e30f, -1e30f };
    float l_i[2] = { 0.f, 0.f };
    float o[8][4] = {};

    #pragma unroll 1
    for (int i = 0; i < 16; i++) {
        const int buf = i & 1;
        cp_wait<1>();
        __syncthreads();

        const uint32_t* K = Ks[buf];
        const uint32_t* V = Vs[buf];

        // ---- S = Q^T K ----
        float sf[8][4] = {};
        #pragma unroll
        for (int ks = 0; ks < 8; ks++) {
            uint32_t a[4];
            int c = ks * 8 + qc;
            a[0] = Qs[c * 68 + q0 + qr];
            a[1] = Qs[c * 68 + q0 + qr + 8];
            a[2] = Qs[(c + 4) * 68 + q0 + qr];
            a[3] = Qs[(c + 4) * 68 + q0 + qr + 8];
            #pragma unroll
            for (int nf = 0; nf < 8; nf++) {
                uint32_t bb[2];
                int s = nf * 8 + qr;
                bb[0] = K[c * 68 + s];
                bb[1] = K[(c + 4) * 68 + s];
                mma_tf32(sf[nf], a, bb);
            }
        }
        // scale 1/8 (q*scale . k*scale, scale=ch^-0.25, product = 1/8)
        #pragma unroll
        for (int nf = 0; nf < 8; nf++) {
            sf[nf][0] *= 0.125f; sf[nf][1] *= 0.125f;
            sf[nf][2] *= 0.125f; sf[nf][3] *= 0.125f;
        }

        // ---- online softmax ----
        float mx0 = -1e30f, mx1 = -1e30f;
        #pragma unroll
        for (int nf = 0; nf < 8; nf++) {
            mx0 = fmaxf(mx0, fmaxf(sf[nf][0], sf[nf][1]));
            mx1 = fmaxf(mx1, fmaxf(sf[nf][2], sf[nf][3]));
        }
        #pragma unroll
        for (int off = 1; off <= 2; off <<= 1) {
            mx0 = fmaxf(mx0, __shfl_xor_sync(0xffffffffu, mx0, off));
            mx1 = fmaxf(mx1, __shfl_xor_sync(0xffffffffu, mx1, off));
        }
        float nm0 = fmaxf(m_i[0], mx0), nm1 = fmaxf(m_i[1], mx1);
        float corr0 = __expf(m_i[0] - nm0), corr1 = __expf(m_i[1] - nm1);
        m_i[0] = nm0; m_i[1] = nm1;
        float sum0 = 0.f, sum1 = 0.f;
        #pragma unroll
        for (int nf = 0; nf < 8; nf++) {
            sf[nf][0] = __expf(sf[nf][0] - nm0);
            sf[nf][1] = __expf(sf[nf][1] - nm0);
            sf[nf][2] = __expf(sf[nf][2] - nm1);
            sf[nf][3] = __expf(sf[nf][3] - nm1);
            sum0 += sf[nf][0] + sf[nf][1];
            sum1 += sf[nf][2] + sf[nf][3];
        }
        #pragma unroll
        for (int off = 1; off <= 2; off <<= 1) {
            sum0 += __shfl_xor_sync(0xffffffffu, sum0, off);
            sum1 += __shfl_xor_sync(0xffffffffu, sum1, off);
        }
        l_i[0] = l_i[0] * corr0 + sum0;
        l_i[1] = l_i[1] * corr1 + sum1;
        #pragma unroll
        for (int nf = 0; nf < 8; nf++) {
            o[nf][0] *= corr0; o[nf][1] *= corr0;
            o[nf][2] *= corr1; o[nf][3] *= corr1;
        }

        // ---- P -> warp-private smem ----
        #pragma unroll
        for (int nf = 0; nf < 8; nf++) {
            int sc = nf * 8 + 2 * qc;
            Ps[(q0 + qr) * 68 + sc]         = f2tf32(sf[nf][0]);
            Ps[(q0 + qr) * 68 + sc + 1]     = f2tf32(sf[nf][1]);
            Ps[(q0 + qr + 8) * 68 + sc]     = f2tf32(sf[nf][2]);
            Ps[(q0 + qr + 8) * 68 + sc + 1] = f2tf32(sf[nf][3]);
        }
        __syncwarp();

        // ---- O += P V^T ----
        #pragma unroll
        for (int ks = 0; ks < 8; ks++) {
            uint32_t a[4];
            int s = ks * 8 + qc;
            a[0] = Ps[(q0 + qr) * 68 + s];
            a[1] = Ps[(q0 + qr + 8) * 68 + s];
            a[2] = Ps[(q0 + qr) * 68 + s + 4];
            a[3] = Ps[(q0 + qr + 8) * 68 + s + 4];
            #pragma unroll
            for (int nf = 0; nf < 8; nf++) {
                uint32_t bb[2];
                int c = nf * 8 + qr;
                bb[0] = V[c * 68 + s];
                bb[1] = V[c * 68 + s + 4];
                mma_tf32(o[nf], a, bb);
            }
        }
        __syncthreads();  // all warps done with buf before overwrite
        if (i + 2 < 16) ISSUE_KV(buf, (i + 2) << 6);
        cp_commit();
    }

    // ---- epilogue: normalize, tf32-convert, stage [c][t], store ----
    float inv0 = 1.f / l_i[0], inv1 = 1.f / l_i[1];
    __syncthreads();
    float* Os = (float*)Qs;
    #pragma unroll
    for (int nf = 0; nf < 8; nf++) {
        int c = nf * 8 + 2 * qc;
        Os[c * 68 + q0 + qr]           = tf32f(o[nf][0] * inv0);
        Os[(c + 1) * 68 + q0 + qr]     = tf32f(o[nf][1] * inv0);
        Os[c * 68 + q0 + qr + 8]       = tf32f(o[nf][2] * inv1);
        Os[(c + 1) * 68 + q0 + qr + 8] = tf32f(o[nf][3] * inv1);
    }
    __syncthreads();
    float* outp = g_attn + ((size_t)b * NC + (size_t)h * NCH) * NT;
    #pragma unroll
    for (int r = 0; r < 8; r++) {
        int idx = tid + (r << 7);
        int c = idx >> 4, t4 = (idx & 15) << 2;
        *(float4*)(outp + (size_t)c * NT + qt0 + t4) = *(const float4*)&Os[c * 68 + t4];
    }
}

// ---------------- launch ----------------
extern "C" void kernel_launch(void* const* d_in, const int* in_sizes, int n_in,
                              void* d_out, int out_size) {
    const float* x      = (const float*)d_in[0];
    const float* norm_w = (const float*)d_in[1];
    const float* norm_b = (const float*)d_in[2];
    const float* qkv_w  = (const float*)d_in[3];
    const float* qkv_b  = (const float*)d_in[4];
    const float* proj_w = (const float*)d_in[5];
    const float* proj_b = (const float*)d_in[6];
    float* out = (float*)d_out;

    float *xn_p, *wq_p, *wp_p, *qkv_p, *attn_p;
    cudaGetSymbolAddress((void**)&xn_p, g_xn);
    cudaGetSymbolAddress((void**)&wq_p, g_wq);
    cudaGetSymbolAddress((void**)&wp_p, g_wp);
    cudaGetSymbolAddress((void**)&qkv_p, g_qkv);
    cudaGetSymbolAddress((void**)&attn_p, g_attn);

    const int gemm_smem = 3 * 8960 * 4;   // 107520
    cudaFuncSetAttribute(mma_gemm_kernel<3 * NC, true, false>,
                         cudaFuncAttributeMaxDynamicSharedMemorySize, gemm_smem);
    cudaFuncSetAttribute(mma_gemm_kernel<NC, false, true>,
                         cudaFuncAttributeMaxDynamicSharedMemorySize, gemm_smem);
    const int attn_smem = 6 * 4352 * 4;   // 104448
    cudaFuncSetAttribute(attn_kernel, cudaFuncAttributeMaxDynamicSharedMemorySize, attn_smem);

    conv_kernel<<<(3 * NC * NC / 4 + 255) / 256, 256>>>(qkv_w, wq_p, 3 * NC * NC / 4);
    conv_kernel<<<(NC * NC / 4 + 255) / 256, 256>>>(proj_w, wp_p, NC * NC / 4);
    gn_kernel<<<NB * NGROUPS, 256>>>(x, norm_w, norm_b);

    dim3 gq(NT / 128, (3 * NC) / 128, NB);
    mma_gemm_kernel<3 * NC, true, false><<<gq, 256, gemm_smem>>>(
        wq_p, xn_p, qkv_b, nullptr, qkv_p);

    dim3 ga(NT / 64, NB * NHEADS);
    attn_kernel<<<ga, 128, attn_smem>>>();

    dim3 gp(NT / 128, NC / 128, NB);
    mma_gemm_kernel<NC, false, true><<<gp, 256, gemm_smem>>>(
        wp_p, attn_p, proj_b, x, out);
}

// round 5
// speedup vs baseline: 3.0913x; 1.0904x over previous
#include <cuda_runtime.h>
#include <cstdint>

#define NB 8
#define NC 512
#define NT 1024
#define NHEADS 8
#define NCH 64
#define NGROUPS 32
#define NGC 16

// ---------------- scratch (alloc-free: __device__ globals) ----------------
__device__ float g_xn[(size_t)NB * NC * NT];        // 16 MB, tf32 bits (natural [b][c][t])
__device__ float g_wq[(size_t)3 * NC * NC];         // 3 MB,  tf32 bits, A-frag-ready
__device__ float g_wp[(size_t)NC * NC];             // 1 MB,  tf32 bits, A-frag-ready
__device__ float g_qkv[(size_t)NB * 3 * NC * NT];   // 48 MB, tf32 bits
__device__ float g_attn[(size_t)NB * NC * NT];      // 16 MB, tf32 bits

// ---------------- helpers ----------------
__device__ __forceinline__ uint32_t f2tf32(float f) {
    uint32_t r;
    asm("cvt.rna.tf32.f32 %0, %1;" : "=r"(r) : "f"(f));
    return r;
}
__device__ __forceinline__ float tf32f(float f) { return __uint_as_float(f2tf32(f)); }
__device__ __forceinline__ void mma_tf32(float* d, const uint32_t* a, const uint32_t* b) {
    asm volatile(
        "mma.sync.aligned.m16n8k8.row.col.f32.tf32.tf32.f32 "
        "{%0,%1,%2,%3}, {%4,%5,%6,%7}, {%8,%9}, {%0,%1,%2,%3};"
        : "+f"(d[0]), "+f"(d[1]), "+f"(d[2]), "+f"(d[3])
        : "r"(a[0]), "r"(a[1]), "r"(a[2]), "r"(a[3]), "r"(b[0]), "r"(b[1]));
}
__device__ __forceinline__ void cp16(uint32_t dst, const void* src) {
    asm volatile("cp.async.cg.shared.global [%0], [%1], 16;" :: "r"(dst), "l"(src));
}
__device__ __forceinline__ void cp_commit() {
    asm volatile("cp.async.commit_group;" ::: "memory");
}
template <int N>
__device__ __forceinline__ void cp_wait() {
    asm volatile("cp.async.wait_group %0;" :: "n"(N) : "memory");
}

// ---------------- weight permute: fp32 [M][NC] -> tf32 A-frag-ready ----------------
// Tile (mt 128, kt 32) stored contiguously (4096 words) at ((mt*16+kt)<<12):
//   word = (ks*8 + mb)*128 + lane*4 + e ; lane=(qr*4+qc)
//   e0 = W[mb16+qr][ks8+qc], e1 = [qr+8][qc], e2 = [qr][qc+4], e3 = [qr+8][qc+4]
__global__ __launch_bounds__(256) void wperm_kernel(const float* __restrict__ in,
                                                    float* __restrict__ out, int M) {
    int i = blockIdx.x * 256 + threadIdx.x;
    if (i >= M * NC) return;
    int m = i >> 9, k = i & 511;
    float v = tf32f(in[i]);
    int mt = m >> 7, mb = (m >> 4) & 7, r = m & 15, qr = r & 7;
    int kt = k >> 5, ks = (k >> 3) & 3, kc = k & 7, qc = kc & 3;
    int e = (r >> 3) | ((kc >> 2) << 1);
    size_t dst = ((size_t)(mt * 16 + kt) << 12) + ((ks * 8 + mb) << 7) + ((qr * 4 + qc) << 2) + e;
    out[dst] = v;
}

// ---------------- GroupNorm: stats + apply + tf32 convert ----------------
__global__ __launch_bounds__(256) void gn_kernel(const float* __restrict__ x,
                                                 const float* __restrict__ nw,
                                                 const float* __restrict__ nb) {
    int bg = blockIdx.x;
    int g = bg & (NGROUPS - 1);
    const float4* p4 = (const float4*)(x + (size_t)bg * NGC * NT);
    float4* o4 = (float4*)(g_xn + (size_t)bg * NGC * NT);
    float s = 0.f, ss = 0.f;
    for (int i = threadIdx.x; i < NGC * NT / 4; i += 256) {
        float4 v = p4[i];
        s  += v.x + v.y + v.z + v.w;
        ss += v.x * v.x + v.y * v.y + v.z * v.z + v.w * v.w;
    }
    __shared__ float sh[512];
    sh[threadIdx.x] = s;
    sh[256 + threadIdx.x] = ss;
    __syncthreads();
    for (int off = 128; off > 0; off >>= 1) {
        if (threadIdx.x < off) {
            sh[threadIdx.x]       += sh[threadIdx.x + off];
            sh[256 + threadIdx.x] += sh[256 + threadIdx.x + off];
        }
        __syncthreads();
    }
    float inv = 1.f / (float)(NGC * NT);
    float mu  = sh[0] * inv;
    float var = sh[256] * inv - mu * mu;
    float rs = rsqrtf(var + 1e-5f);
    for (int i = threadIdx.x; i < NGC * NT / 4; i += 256) {
        int c = g * NGC + (i >> 8);
        float sw = nw[c] * rs, sb = nb[c] - mu * sw;
        float4 v = p4[i];
        v.x = tf32f(v.x * sw + sb); v.y = tf32f(v.y * sw + sb);
        v.z = tf32f(v.z * sw + sb); v.w = tf32f(v.w * sw + sb);
        o4[i] = v;
    }
}

// ---------------- TF32 mma.sync GEMM, 3-stage cp.async, frag-ready A ----------------
// Block 128x128, BK=32, 8 warps, warptile 64x32.
// Stage: A 4096 w (frag-ready) + B [32][136] 4352 w = 8448 w.
template <int MTOT, bool OUT_TF32, bool FUSE_RES>
__global__ __launch_bounds__(256, 2) void mma_gemm_kernel(
    const float* __restrict__ W, const float* __restrict__ Bsrc,
    const float* __restrict__ bias,
    const float* __restrict__ resid, float* __restrict__ Cout)
{
    extern __shared__ uint32_t smu[];
    const uint32_t sbase = (uint32_t)__cvta_generic_to_shared(smu);
    const int b = blockIdx.z, m0 = blockIdx.y << 7, n0 = blockIdx.x << 7;
    const float* Bb = Bsrc + (size_t)b * NC * NT;
    const float* Wt0 = W + ((size_t)(m0 >> 7) << 4 << 12);  // (mt*16) tiles
    const int tid = threadIdx.x, lane = tid & 31, warp = tid >> 5;
    const int wm = warp >> 2, wn = warp & 3;
    const int qr = lane >> 2, qc = lane & 3;

    auto ISSUE = [&](int stage, int it) {
        uint32_t abase = sbase + (uint32_t)stage * 8448u * 4u;
        uint32_t bbase = abase + 4096u * 4u;
        const float* Wt = Wt0 + ((size_t)it << 12);
        const int k0 = it << 5;
        #pragma unroll
        for (int r = 0; r < 4; r++) {
            int idx = tid + (r << 8);
            cp16(abase + (uint32_t)idx * 16u, Wt + idx * 4);
            int k = idx >> 5, n4 = (idx & 31) << 2;
            cp16(bbase + ((uint32_t)k * 136u + n4) * 4u,
                 Bb + (size_t)(k0 + k) * NT + n0 + n4);
        }
    };

    float acc[4][4][4] = {};

    ISSUE(0, 0); cp_commit();
    ISSUE(1, 1); cp_commit();

    #pragma unroll 1
    for (int it = 0; it < 16; it++) {
        cp_wait<1>();
        __syncthreads();
        if (it + 2 < 16) ISSUE((it + 2) % 3, it + 2);
        cp_commit();

        const uint32_t* A  = smu + (it % 3) * 8448;
        const uint32_t* Bs = A + 4096;
        #pragma unroll
        for (int ks = 0; ks < 4; ks++) {
            uint4 af[4];
            uint32_t bf[4][2];
            #pragma unroll
            for (int mf = 0; mf < 4; mf++)
                af[mf] = *(const uint4*)&A[((ks * 8 + wm * 4 + mf) << 7) + (lane << 2)];
            #pragma unroll
            for (int nf = 0; nf < 4; nf++) {
                int n = wn * 32 + nf * 8 + qr, k = ks * 8 + qc;
                bf[nf][0] = Bs[k * 136 + n];
                bf[nf][1] = Bs[(k + 4) * 136 + n];
            }
            #pragma unroll
            for (int mf = 0; mf < 4; mf++)
                #pragma unroll
                for (int nf = 0; nf < 4; nf++)
                    mma_tf32(acc[mf][nf], (const uint32_t*)&af[mf], bf[nf]);
        }
    }

    // epilogue
    #pragma unroll
    for (int mf = 0; mf < 4; mf++) {
        int m_r = m0 + wm * 64 + mf * 16 + qr;
        float bv0 = bias[m_r], bv1 = bias[m_r + 8];
        #pragma unroll
        for (int nf = 0; nf < 4; nf++) {
            int n = n0 + wn * 32 + nf * 8 + 2 * qc;
            float2 v0 = { acc[mf][nf][0] + bv0, acc[mf][nf][1] + bv0 };
            float2 v1 = { acc[mf][nf][2] + bv1, acc[mf][nf][3] + bv1 };
            if (FUSE_RES) {
                float2 r0 = *(const float2*)(resid + ((size_t)b * NC + m_r) * NT + n);
                float2 r1 = *(const float2*)(resid + ((size_t)b * NC + m_r + 8) * NT + n);
                v0.x += r0.x; v0.y += r0.y;
                v1.x += r1.x; v1.y += r1.y;
            }
            if (OUT_TF32) {
                v0.x = tf32f(v0.x); v0.y = tf32f(v0.y);
                v1.x = tf32f(v1.x); v1.y = tf32f(v1.y);
            }
            *(float2*)(Cout + ((size_t)b * MTOT + m_r) * NT + n) = v0;
            *(float2*)(Cout + ((size_t)b * MTOT + m_r + 8) * NT + n) = v1;
        }
    }
}

// ---------------- flash attention: Q-frags hoisted, cp.async dbl-buffered K/V ----------------
// 128 threads (4 warps), 64-q tile, 64-s chunks. smem slots (4352 w each):
//   0: Q stage -> P ( [64][68] )   1,2: K bufs   3,4: V bufs
__global__ __launch_bounds__(128, 2) void attn_kernel() {
    extern __shared__ uint32_t smw[];
    const uint32_t sbase = (uint32_t)__cvta_generic_to_shared(smw);
    uint32_t* const P0 = smw;  // Q stage, then P, then O stage
    uint32_t* const Ks[2] = { smw + 4352, smw + 2 * 4352 };
    uint32_t* const Vs[2] = { smw + 3 * 4352, smw + 4 * 4352 };

    const int qt0 = blockIdx.x << 6;
    const int bh = blockIdx.y;
    const int b = bh >> 3, h = bh & 7;
    const float* qp = g_qkv + ((size_t)b * 3 * NC + (size_t)h * 3 * NCH) * NT;
    const float* kp = qp + (size_t)NCH * NT;
    const float* vp = kp + (size_t)NCH * NT;

    const int tid = threadIdx.x, lane = tid & 31, w = tid >> 5;
    const int qr = lane >> 2, qc = lane & 3;
    const int q0 = w << 4;

    auto ISSUE_KV = [&](int buf, int s0) {
        uint32_t kb = sbase + (1u + (uint32_t)buf) * 4352u * 4u;
        uint32_t vb = sbase + (3u + (uint32_t)buf) * 4352u * 4u;
        #pragma unroll
        for (int r = 0; r < 8; r++) {
            int idx = tid + (r << 7);
            int c = idx >> 4, s4 = (idx & 15) << 2;
            uint32_t off = ((uint32_t)c * 68u + s4) * 4u;
            cp16(kb + off, kp + (size_t)c * NT + s0 + s4);
            cp16(vb + off, vp + (size_t)c * NT + s0 + s4);
        }
    };

    // prologue: Q (g0), KV0 (g1), KV1 (g2)
    #pragma unroll
    for (int r = 0; r < 8; r++) {
        int idx = tid + (r << 7);
        int c = idx >> 4, t4 = (idx & 15) << 2;
        cp16(sbase + ((uint32_t)c * 68u + t4) * 4u, qp + (size_t)c * NT + qt0 + t4);
    }
    cp_commit();
    ISSUE_KV(0, 0); cp_commit();
    ISSUE_KV(1, 64); cp_commit();

    // hoist Q fragments (loop-invariant) to registers
    cp_wait<2>();
    __syncthreads();
    uint32_t qf[8][4];
    #pragma unroll
    for (int ks = 0; ks < 8; ks++) {
        int c = ks * 8 + qc;
        qf[ks][0] = P0[c * 68 + q0 + qr];
        qf[ks][1] = P0[c * 68 + q0 + qr + 8];
        qf[ks][2] = P0[(c + 4) * 68 + q0 + qr];
        qf[ks][3] = P0[(c + 4) * 68 + q0 + qr + 8];
    }
    __syncthreads();  // all Q-frag reads done before P0 reused for P

    float m_i[2] = { -1e30f, -1e30f };
    float l_i[2] = { 0.f, 0.f };
    float o[8][4] = {};

    #pragma unroll 1
    for (int i = 0; i < 16; i++) {
        const int buf = i & 1;
        cp_wait<1>();
        __syncthreads();

        const uint32_t* K = Ks[buf];
        const uint32_t* V = Vs[buf];

        // ---- S = Q^T K ----
        float sf[8][4] = {};
        #pragma unroll
        for (int ks = 0; ks < 8; ks++) {
            int c = ks * 8 + qc;
            #pragma unroll
            for (int nf = 0; nf < 8; nf++) {
                uint32_t bb[2];
                int s = nf * 8 + qr;
                bb[0] = K[c * 68 + s];
                bb[1] = K[(c + 4) * 68 + s];
                mma_tf32(sf[nf], qf[ks], bb);
            }
        }
        #pragma unroll
        for (int nf = 0; nf < 8; nf++) {
            sf[nf][0] *= 0.125f; sf[nf][1] *= 0.125f;
            sf[nf][2] *= 0.125f; sf[nf][3] *= 0.125f;
        }

        // ---- online softmax ----
        float mx0 = -1e30f, mx1 = -1e30f;
        #pragma unroll
        for (int nf = 0; nf < 8; nf++) {
            mx0 = fmaxf(mx0, fmaxf(sf[nf][0], sf[nf][1]));
            mx1 = fmaxf(mx1, fmaxf(sf[nf][2], sf[nf][3]));
        }
        #pragma unroll
        for (int off = 1; off <= 2; off <<= 1) {
            mx0 = fmaxf(mx0, __shfl_xor_sync(0xffffffffu, mx0, off));
            mx1 = fmaxf(mx1, __shfl_xor_sync(0xffffffffu, mx1, off));
        }
        float nm0 = fmaxf(m_i[0], mx0), nm1 = fmaxf(m_i[1], mx1);
        float corr0 = __expf(m_i[0] - nm0), corr1 = __expf(m_i[1] - nm1);
        m_i[0] = nm0; m_i[1] = nm1;
        float sum0 = 0.f, sum1 = 0.f;
        #pragma unroll
        for (int nf = 0; nf < 8; nf++) {
            sf[nf][0] = __expf(sf[nf][0] - nm0);
            sf[nf][1] = __expf(sf[nf][1] - nm0);
            sf[nf][2] = __expf(sf[nf][2] - nm1);
            sf[nf][3] = __expf(sf[nf][3] - nm1);
            sum0 += sf[nf][0] + sf[nf][1];
            sum1 += sf[nf][2] + sf[nf][3];
        }
        #pragma unroll
        for (int off = 1; off <= 2; off <<= 1) {
            sum0 += __shfl_xor_sync(0xffffffffu, sum0, off);
            sum1 += __shfl_xor_sync(0xffffffffu, sum1, off);
        }
        l_i[0] = l_i[0] * corr0 + sum0;
        l_i[1] = l_i[1] * corr1 + sum1;
        #pragma unroll
        for (int nf = 0; nf < 8; nf++) {
            o[nf][0] *= corr0; o[nf][1] *= corr0;
            o[nf][2] *= corr1; o[nf][3] *= corr1;
        }

        // ---- P -> warp-private smem (STS.64) ----
        #pragma unroll
        for (int nf = 0; nf < 8; nf++) {
            int sc = nf * 8 + 2 * qc;
            *(uint2*)&P0[(q0 + qr) * 68 + sc] =
                make_uint2(f2tf32(sf[nf][0]), f2tf32(sf[nf][1]));
            *(uint2*)&P0[(q0 + qr + 8) * 68 + sc] =
                make_uint2(f2tf32(sf[nf][2]), f2tf32(sf[nf][3]));
        }
        __syncwarp();

        // ---- O += P V^T ----
        #pragma unroll
        for (int ks = 0; ks < 8; ks++) {
            uint32_t a[4];
            int s = ks * 8 + qc;
            a[0] = P0[(q0 + qr) * 68 + s];
            a[1] = P0[(q0 + qr + 8) * 68 + s];
            a[2] = P0[(q0 + qr) * 68 + s + 4];
            a[3] = P0[(q0 + qr + 8) * 68 + s + 4];
            #pragma unroll
            for (int nf = 0; nf < 8; nf++) {
                uint32_t bb[2];
                int c = nf * 8 + qr;
                bb[0] = V[c * 68 + s];
                bb[1] = V[c * 68 + s + 4];
                mma_tf32(o[nf], a, bb);
            }
        }
        __syncthreads();
        if (i + 2 < 16) ISSUE_KV(buf, (i + 2) << 6);
        cp_commit();
    }

    // ---- epilogue: normalize, tf32, stage [c][t] in P0, coalesced store ----
    float inv0 = 1.f / l_i[0], inv1 = 1.f / l_i[1];
    __syncthreads();
    float* Os = (float*)P0;
    #pragma unroll
    for (int nf = 0; nf < 8; nf++) {
        int c = nf * 8 + 2 * qc;
        Os[c * 68 + q0 + qr]           = tf32f(o[nf][0] * inv0);
        Os[(c + 1) * 68 + q0 + qr]     = tf32f(o[nf][1] * inv0);
        Os[c * 68 + q0 + qr + 8]       = tf32f(o[nf][2] * inv1);
        Os[(c + 1) * 68 + q0 + qr + 8] = tf32f(o[nf][3] * inv1);
    }
    __syncthreads();
    float* outp = g_attn + ((size_t)b * NC + (size_t)h * NCH) * NT;
    #pragma unroll
    for (int r = 0; r < 8; r++) {
        int idx = tid + (r << 7);
        int c = idx >> 4, t4 = (idx & 15) << 2;
        *(float4*)(outp + (size_t)c * NT + qt0 + t4) = *(const float4*)&Os[c * 68 + t4];
    }
}

// ---------------- launch ----------------
extern "C" void kernel_launch(void* const* d_in, const int* in_sizes, int n_in,
                              void* d_out, int out_size) {
    const float* x      = (const float*)d_in[0];
    const float* norm_w = (const float*)d_in[1];
    const float* norm_b = (const float*)d_in[2];
    const float* qkv_w  = (const float*)d_in[3];
    const float* qkv_b  = (const float*)d_in[4];
    const float* proj_w = (const float*)d_in[5];
    const float* proj_b = (const float*)d_in[6];
    float* out = (float*)d_out;

    float *xn_p, *wq_p, *wp_p, *qkv_p, *attn_p;
    cudaGetSymbolAddress((void**)&xn_p, g_xn);
    cudaGetSymbolAddress((void**)&wq_p, g_wq);
    cudaGetSymbolAddress((void**)&wp_p, g_wp);
    cudaGetSymbolAddress((void**)&qkv_p, g_qkv);
    cudaGetSymbolAddress((void**)&attn_p, g_attn);

    const int gemm_smem = 3 * 8448 * 4;   // 101376
    cudaFuncSetAttribute(mma_gemm_kernel<3 * NC, true, false>,
                         cudaFuncAttributeMaxDynamicSharedMemorySize, gemm_smem);
    cudaFuncSetAttribute(mma_gemm_kernel<NC, false, true>,
                         cudaFuncAttributeMaxDynamicSharedMemorySize, gemm_smem);
    const int attn_smem = 5 * 4352 * 4;   // 87040
    cudaFuncSetAttribute(attn_kernel, cudaFuncAttributeMaxDynamicSharedMemorySize, attn_smem);

    wperm_kernel<<<(3 * NC * NC + 255) / 256, 256>>>(qkv_w, wq_p, 3 * NC);
    wperm_kernel<<<(NC * NC + 255) / 256, 256>>>(proj_w, wp_p, NC);
    gn_kernel<<<NB * NGROUPS, 256>>>(x, norm_w, norm_b);

    dim3 gq(NT / 128, (3 * NC) / 128, NB);
    mma_gemm_kernel<3 * NC, true, false><<<gq, 256, gemm_smem>>>(
        wq_p, xn_p, qkv_b, nullptr, qkv_p);

    dim3 ga(NT / 64, NB * NHEADS);
    attn_kernel<<<ga, 128, attn_smem>>>();

    dim3 gp(NT / 128, NC / 128, NB);
    mma_gemm_kernel<NC, false, true><<<gp, 256, gemm_smem>>>(
        wp_p, attn_p, proj_b, x, out);
}

// round 6
// speedup vs baseline: 3.5651x; 1.1533x over previous
#include <cuda_runtime.h>
#include <cstdint>

#define NB 8
#define NC 512
#define NT 1024
#define NHEADS 8
#define NCH 64
#define NGROUPS 32
#define NGC 16

// ---------------- scratch (alloc-free: __device__ globals) ----------------
__device__ float g_xn[(size_t)NB * NC * NT];        // 16 MB, tf32 bits (natural [b][c][t])
__device__ float g_wq[(size_t)3 * NC * NC];         // 3 MB,  tf32 bits, A-frag-ready
__device__ float g_wp[(size_t)NC * NC];             // 1 MB,  tf32 bits, A-frag-ready
__device__ float g_qkv[(size_t)NB * 3 * NC * NT];   // 48 MB, tf32 bits
__device__ float g_attn[(size_t)NB * NC * NT];      // 16 MB, tf32 bits

// ---------------- helpers ----------------
__device__ __forceinline__ uint32_t f2tf32(float f) {
    uint32_t r;
    asm("cvt.rna.tf32.f32 %0, %1;" : "=r"(r) : "f"(f));
    return r;
}
__device__ __forceinline__ float tf32f(float f) { return __uint_as_float(f2tf32(f)); }
__device__ __forceinline__ void mma_tf32(float* d, const uint32_t* a, const uint32_t* b) {
    asm volatile(
        "mma.sync.aligned.m16n8k8.row.col.f32.tf32.tf32.f32 "
        "{%0,%1,%2,%3}, {%4,%5,%6,%7}, {%8,%9}, {%0,%1,%2,%3};"
        : "+f"(d[0]), "+f"(d[1]), "+f"(d[2]), "+f"(d[3])
        : "r"(a[0]), "r"(a[1]), "r"(a[2]), "r"(a[3]), "r"(b[0]), "r"(b[1]));
}
__device__ __forceinline__ void cp16(uint32_t dst, const void* src) {
    asm volatile("cp.async.cg.shared.global [%0], [%1], 16;" :: "r"(dst), "l"(src));
}
__device__ __forceinline__ void cp_commit() {
    asm volatile("cp.async.commit_group;" ::: "memory");
}
template <int N>
__device__ __forceinline__ void cp_wait() {
    asm volatile("cp.async.wait_group %0;" :: "n"(N) : "memory");
}

// ---------------- weight permute: fp32 [M][NC] -> tf32 A-frag-ready ----------------
__global__ __launch_bounds__(256) void wperm_kernel(const float* __restrict__ in,
                                                    float* __restrict__ out, int M) {
    int i = blockIdx.x * 256 + threadIdx.x;
    if (i >= M * NC) return;
    int m = i >> 9, k = i & 511;
    float v = tf32f(in[i]);
    int mt = m >> 7, mb = (m >> 4) & 7, r = m & 15, qr = r & 7;
    int kt = k >> 5, ks = (k >> 3) & 3, kc = k & 7, qc = kc & 3;
    int e = (r >> 3) | ((kc >> 2) << 1);
    size_t dst = ((size_t)(mt * 16 + kt) << 12) + ((ks * 8 + mb) << 7) + ((qr * 4 + qc) << 2) + e;
    out[dst] = v;
}

// ---------------- GroupNorm: stats + apply + tf32 convert ----------------
__global__ __launch_bounds__(256) void gn_kernel(const float* __restrict__ x,
                                                 const float* __restrict__ nw,
                                                 const float* __restrict__ nb) {
    int bg = blockIdx.x;
    int g = bg & (NGROUPS - 1);
    const float4* p4 = (const float4*)(x + (size_t)bg * NGC * NT);
    float4* o4 = (float4*)(g_xn + (size_t)bg * NGC * NT);
    float s = 0.f, ss = 0.f;
    for (int i = threadIdx.x; i < NGC * NT / 4; i += 256) {
        float4 v = p4[i];
        s  += v.x + v.y + v.z + v.w;
        ss += v.x * v.x + v.y * v.y + v.z * v.z + v.w * v.w;
    }
    __shared__ float sh[512];
    sh[threadIdx.x] = s;
    sh[256 + threadIdx.x] = ss;
    __syncthreads();
    for (int off = 128; off > 0; off >>= 1) {
        if (threadIdx.x < off) {
            sh[threadIdx.x]       += sh[threadIdx.x + off];
            sh[256 + threadIdx.x] += sh[256 + threadIdx.x + off];
        }
        __syncthreads();
    }
    float inv = 1.f / (float)(NGC * NT);
    float mu  = sh[0] * inv;
    float var = sh[256] * inv - mu * mu;
    float rs = rsqrtf(var + 1e-5f);
    for (int i = threadIdx.x; i < NGC * NT / 4; i += 256) {
        int c = g * NGC + (i >> 8);
        float sw = nw[c] * rs, sb = nb[c] - mu * sw;
        float4 v = p4[i];
        v.x = tf32f(v.x * sw + sb); v.y = tf32f(v.y * sw + sb);
        v.z = tf32f(v.z * sw + sb); v.w = tf32f(v.w * sw + sb);
        o4[i] = v;
    }
}

// ---------------- TF32 mma.sync GEMM, 3-stage cp.async, frag-ready A ----------------
template <int MTOT, bool OUT_TF32, bool FUSE_RES>
__global__ __launch_bounds__(256, 2) void mma_gemm_kernel(
    const float* __restrict__ W, const float* __restrict__ Bsrc,
    const float* __restrict__ bias,
    const float* __restrict__ resid, float* __restrict__ Cout)
{
    extern __shared__ uint32_t smu[];
    const uint32_t sbase = (uint32_t)__cvta_generic_to_shared(smu);
    const int b = blockIdx.z, m0 = blockIdx.y << 7, n0 = blockIdx.x << 7;
    const float* Bb = Bsrc + (size_t)b * NC * NT;
    const float* Wt0 = W + ((size_t)(m0 >> 7) << 4 << 12);
    const int tid = threadIdx.x, lane = tid & 31, warp = tid >> 5;
    const int wm = warp >> 2, wn = warp & 3;
    const int qr = lane >> 2, qc = lane & 3;

    auto ISSUE = [&](int stage, int it) {
        uint32_t abase = sbase + (uint32_t)stage * 8448u * 4u;
        uint32_t bbase = abase + 4096u * 4u;
        const float* Wt = Wt0 + ((size_t)it << 12);
        const int k0 = it << 5;
        #pragma unroll
        for (int r = 0; r < 4; r++) {
            int idx = tid + (r << 8);
            cp16(abase + (uint32_t)idx * 16u, Wt + idx * 4);
            int k = idx >> 5, n4 = (idx & 31) << 2;
            cp16(bbase + ((uint32_t)k * 136u + n4) * 4u,
                 Bb + (size_t)(k0 + k) * NT + n0 + n4);
        }
    };

    float acc[4][4][4] = {};

    ISSUE(0, 0); cp_commit();
    ISSUE(1, 1); cp_commit();

    #pragma unroll 1
    for (int it = 0; it < 16; it++) {
        cp_wait<1>();
        __syncthreads();
        if (it + 2 < 16) ISSUE((it + 2) % 3, it + 2);
        cp_commit();

        const uint32_t* A  = smu + (it % 3) * 8448;
        const uint32_t* Bs = A + 4096;
        #pragma unroll
        for (int ks = 0; ks < 4; ks++) {
            uint4 af[4];
            uint32_t bf[4][2];
            #pragma unroll
            for (int mf = 0; mf < 4; mf++)
                af[mf] = *(const uint4*)&A[((ks * 8 + wm * 4 + mf) << 7) + (lane << 2)];
            #pragma unroll
            for (int nf = 0; nf < 4; nf++) {
                int n = wn * 32 + nf * 8 + qr, k = ks * 8 + qc;
                bf[nf][0] = Bs[k * 136 + n];
                bf[nf][1] = Bs[(k + 4) * 136 + n];
            }
            #pragma unroll
            for (int mf = 0; mf < 4; mf++)
                #pragma unroll
                for (int nf = 0; nf < 4; nf++)
                    mma_tf32(acc[mf][nf], (const uint32_t*)&af[mf], bf[nf]);
        }
    }

    #pragma unroll
    for (int mf = 0; mf < 4; mf++) {
        int m_r = m0 + wm * 64 + mf * 16 + qr;
        float bv0 = bias[m_r], bv1 = bias[m_r + 8];
        #pragma unroll
        for (int nf = 0; nf < 4; nf++) {
            int n = n0 + wn * 32 + nf * 8 + 2 * qc;
            float2 v0 = { acc[mf][nf][0] + bv0, acc[mf][nf][1] + bv0 };
            float2 v1 = { acc[mf][nf][2] + bv1, acc[mf][nf][3] + bv1 };
            if (FUSE_RES) {
                float2 r0 = *(const float2*)(resid + ((size_t)b * NC + m_r) * NT + n);
                float2 r1 = *(const float2*)(resid + ((size_t)b * NC + m_r + 8) * NT + n);
                v0.x += r0.x; v0.y += r0.y;
                v1.x += r1.x; v1.y += r1.y;
            }
            if (OUT_TF32) {
                v0.x = tf32f(v0.x); v0.y = tf32f(v0.y);
                v1.x = tf32f(v1.x); v1.y = tf32f(v1.y);
            }
            *(float2*)(Cout + ((size_t)b * MTOT + m_r) * NT + n) = v0;
            *(float2*)(Cout + ((size_t)b * MTOT + m_r + 8) * NT + n) = v1;
        }
    }
}

// ---------------- flash attention: 128-q tile, 32 q/warp (2 m-frags), 32-s chunks ----------------
// smem (words): slot0 [0,8448): Q stage [64][132] -> P [128][36] -> O stage [64][132]
//               K bufs 2x2304 at 8448, V bufs 2x2304 after.
__global__ __launch_bounds__(128, 2) void attn_kernel() {
    extern __shared__ uint32_t smw[];
    const uint32_t sbase = (uint32_t)__cvta_generic_to_shared(smw);
    uint32_t* const P0 = smw;
    uint32_t* const Ks[2] = { smw + 8448, smw + 8448 + 2304 };
    uint32_t* const Vs[2] = { smw + 8448 + 2 * 2304, smw + 8448 + 3 * 2304 };

    const int qt0 = blockIdx.x << 7;
    const int bh = blockIdx.y;
    const int b = bh >> 3, h = bh & 7;
    const float* qp = g_qkv + ((size_t)b * 3 * NC + (size_t)h * 3 * NCH) * NT;
    const float* kp = qp + (size_t)NCH * NT;
    const float* vp = kp + (size_t)NCH * NT;

    const int tid = threadIdx.x, lane = tid & 31, w = tid >> 5;
    const int qr = lane >> 2, qc = lane & 3;
    const int q0 = w << 5;   // 32 queries per warp

    auto ISSUE_KV = [&](int buf, int s0) {
        uint32_t kb = sbase + (8448u + (uint32_t)buf * 2304u) * 4u;
        uint32_t vb = sbase + (8448u + (2u + (uint32_t)buf) * 2304u) * 4u;
        #pragma unroll
        for (int r = 0; r < 4; r++) {
            int idx = tid + (r << 7);
            int c = idx >> 3, s4 = (idx & 7) << 2;
            uint32_t off = ((uint32_t)c * 36u + s4) * 4u;
            cp16(kb + off, kp + (size_t)c * NT + s0 + s4);
            cp16(vb + off, vp + (size_t)c * NT + s0 + s4);
        }
    };

    // prologue: Q fill [64][132]
    #pragma unroll
    for (int r = 0; r < 16; r++) {
        int idx = tid + (r << 7);
        int c = idx >> 5, t4 = (idx & 31) << 2;
        cp16(sbase + ((uint32_t)c * 132u + t4) * 4u, qp + (size_t)c * NT + qt0 + t4);
    }
    cp_commit();
    ISSUE_KV(0, 0); cp_commit();
    ISSUE_KV(1, 32); cp_commit();

    // hoist Q fragments, scaled by 1/8 (exponent-only: exact in tf32)
    cp_wait<2>();
    __syncthreads();
    uint32_t qf[2][8][4];
    #pragma unroll
    for (int ks = 0; ks < 8; ks++) {
        int c = ks * 8 + qc;
        #pragma unroll
        for (int mf = 0; mf < 2; mf++) {
            int qq = q0 + mf * 16 + qr;
            qf[mf][ks][0] = __float_as_uint(__uint_as_float(P0[c * 132 + qq]) * 0.125f);
            qf[mf][ks][1] = __float_as_uint(__uint_as_float(P0[c * 132 + qq + 8]) * 0.125f);
            qf[mf][ks][2] = __float_as_uint(__uint_as_float(P0[(c + 4) * 132 + qq]) * 0.125f);
            qf[mf][ks][3] = __float_as_uint(__uint_as_float(P0[(c + 4) * 132 + qq + 8]) * 0.125f);
        }
    }

    float m_i[2][2] = {{-1e30f, -1e30f}, {-1e30f, -1e30f}};
    float l_i[2][2] = {{0.f, 0.f}, {0.f, 0.f}};
    float o[2][8][4] = {};

    #pragma unroll 1
    for (int i = 0; i < 32; i++) {
        const int buf = i & 1;
        cp_wait<1>();
        __syncthreads();   // also orders Q-frag reads (i=0) before P0 reuse

        const uint32_t* K = Ks[buf];
        const uint32_t* V = Vs[buf];

        // ---- S = (Q/8)^T K : 2 m-frags share each K-frag ----
        float sf[2][4][4] = {};
        #pragma unroll
        for (int ks = 0; ks < 8; ks++) {
            int c = ks * 8 + qc;
            #pragma unroll
            for (int nf = 0; nf < 4; nf++) {
                uint32_t bb[2];
                int s = nf * 8 + qr;
                bb[0] = K[c * 36 + s];
                bb[1] = K[(c + 4) * 36 + s];
                mma_tf32(sf[0][nf], qf[0][ks], bb);
                mma_tf32(sf[1][nf], qf[1][ks], bb);
            }
        }

        // ---- online softmax (per m-frag, rows qr / qr+8, quad shuffles) ----
        #pragma unroll
        for (int mf = 0; mf < 2; mf++) {
            float mx0 = -1e30f, mx1 = -1e30f;
            #pragma unroll
            for (int nf = 0; nf < 4; nf++) {
                mx0 = fmaxf(mx0, fmaxf(sf[mf][nf][0], sf[mf][nf][1]));
                mx1 = fmaxf(mx1, fmaxf(sf[mf][nf][2], sf[mf][nf][3]));
            }
            #pragma unroll
            for (int off = 1; off <= 2; off <<= 1) {
                mx0 = fmaxf(mx0, __shfl_xor_sync(0xffffffffu, mx0, off));
                mx1 = fmaxf(mx1, __shfl_xor_sync(0xffffffffu, mx1, off));
            }
            float nm0 = fmaxf(m_i[mf][0], mx0), nm1 = fmaxf(m_i[mf][1], mx1);
            float corr0 = __expf(m_i[mf][0] - nm0), corr1 = __expf(m_i[mf][1] - nm1);
            m_i[mf][0] = nm0; m_i[mf][1] = nm1;
            float sum0 = 0.f, sum1 = 0.f;
            #pragma unroll
            for (int nf = 0; nf < 4; nf++) {
                sf[mf][nf][0] = __expf(sf[mf][nf][0] - nm0);
                sf[mf][nf][1] = __expf(sf[mf][nf][1] - nm0);
                sf[mf][nf][2] = __expf(sf[mf][nf][2] - nm1);
                sf[mf][nf][3] = __expf(sf[mf][nf][3] - nm1);
                sum0 += sf[mf][nf][0] + sf[mf][nf][1];
                sum1 += sf[mf][nf][2] + sf[mf][nf][3];
            }
            #pragma unroll
            for (int off = 1; off <= 2; off <<= 1) {
                sum0 += __shfl_xor_sync(0xffffffffu, sum0, off);
                sum1 += __shfl_xor_sync(0xffffffffu, sum1, off);
            }
            l_i[mf][0] = l_i[mf][0] * corr0 + sum0;
            l_i[mf][1] = l_i[mf][1] * corr1 + sum1;
            #pragma unroll
            for (int nf = 0; nf < 8; nf++) {
                o[mf][nf][0] *= corr0; o[mf][nf][1] *= corr0;
                o[mf][nf][2] *= corr1; o[mf][nf][3] *= corr1;
            }
        }

        // ---- P -> warp-private smem rows [q0, q0+32), stride 36 (STS.64) ----
        #pragma unroll
        for (int mf = 0; mf < 2; mf++) {
            int qq = q0 + mf * 16 + qr;
            #pragma unroll
            for (int nf = 0; nf < 4; nf++) {
                int sc = nf * 8 + 2 * qc;
                *(uint2*)&P0[qq * 36 + sc] =
                    make_uint2(f2tf32(sf[mf][nf][0]), f2tf32(sf[mf][nf][1]));
                *(uint2*)&P0[(qq + 8) * 36 + sc] =
                    make_uint2(f2tf32(sf[mf][nf][2]), f2tf32(sf[mf][nf][3]));
            }
        }
        __syncwarp();

        // ---- O += P V^T : 2 m-frags share each V-frag ----
        #pragma unroll
        for (int ks = 0; ks < 4; ks++) {
            int s = ks * 8 + qc;
            uint32_t a0[4], a1[4];
            {
                int qq = q0 + qr;
                a0[0] = P0[qq * 36 + s];       a0[1] = P0[(qq + 8) * 36 + s];
                a0[2] = P0[qq * 36 + s + 4];   a0[3] = P0[(qq + 8) * 36 + s + 4];
                qq = q0 + 16 + qr;
                a1[0] = P0[qq * 36 + s];       a1[1] = P0[(qq + 8) * 36 + s];
                a1[2] = P0[qq * 36 + s + 4];   a1[3] = P0[(qq + 8) * 36 + s + 4];
            }
            #pragma unroll
            for (int nf = 0; nf < 8; nf++) {
                uint32_t bb[2];
                int c = nf * 8 + qr;
                bb[0] = V[c * 36 + s];
                bb[1] = V[c * 36 + s + 4];
                mma_tf32(o[0][nf], a0, bb);
                mma_tf32(o[1][nf], a1, bb);
            }
        }
        __syncthreads();   // all warps done with buf before refill
        if (i + 2 < 32) ISSUE_KV(buf, (i + 2) << 5);
        cp_commit();
    }

    // ---- epilogue: normalize, tf32, stage [c][t] stride 132, coalesced store ----
    float inv00 = 1.f / l_i[0][0], inv01 = 1.f / l_i[0][1];
    float inv10 = 1.f / l_i[1][0], inv11 = 1.f / l_i[1][1];
    __syncthreads();
    float* Os = (float*)P0;
    #pragma unroll
    for (int mf = 0; mf < 2; mf++) {
        float i0 = mf ? inv10 : inv00, i1 = mf ? inv11 : inv01;
        int qq = q0 + mf * 16 + qr;
        #pragma unroll
        for (int nf = 0; nf < 8; nf++) {
            int c = nf * 8 + 2 * qc;
            Os[c * 132 + qq]           = tf32f(o[mf][nf][0] * i0);
            Os[(c + 1) * 132 + qq]     = tf32f(o[mf][nf][1] * i0);
            Os[c * 132 + qq + 8]       = tf32f(o[mf][nf][2] * i1);
            Os[(c + 1) * 132 + qq + 8] = tf32f(o[mf][nf][3] * i1);
        }
    }
    __syncthreads();
    float* outp = g_attn + ((size_t)b * NC + (size_t)h * NCH) * NT;
    #pragma unroll
    for (int r = 0; r < 16; r++) {
        int idx = tid + (r << 7);
        int c = idx >> 5, t4 = (idx & 31) << 2;
        *(float4*)(outp + (size_t)c * NT + qt0 + t4) = *(const float4*)&Os[c * 132 + t4];
    }
}

// ---------------- launch ----------------
extern "C" void kernel_launch(void* const* d_in, const int* in_sizes, int n_in,
                              void* d_out, int out_size) {
    const float* x      = (const float*)d_in[0];
    const float* norm_w = (const float*)d_in[1];
    const float* norm_b = (const float*)d_in[2];
    const float* qkv_w  = (const float*)d_in[3];
    const float* qkv_b  = (const float*)d_in[4];
    const float* proj_w = (const float*)d_in[5];
    const float* proj_b = (const float*)d_in[6];
    float* out = (float*)d_out;

    float *xn_p, *wq_p, *wp_p, *qkv_p, *attn_p;
    cudaGetSymbolAddress((void**)&xn_p, g_xn);
    cudaGetSymbolAddress((void**)&wq_p, g_wq);
    cudaGetSymbolAddress((void**)&wp_p, g_wp);
    cudaGetSymbolAddress((void**)&qkv_p, g_qkv);
    cudaGetSymbolAddress((void**)&attn_p, g_attn);

    const int gemm_smem = 3 * 8448 * 4;   // 101376
    cudaFuncSetAttribute(mma_gemm_kernel<3 * NC, true, false>,
                         cudaFuncAttributeMaxDynamicSharedMemorySize, gemm_smem);
    cudaFuncSetAttribute(mma_gemm_kernel<NC, false, true>,
                         cudaFuncAttributeMaxDynamicSharedMemorySize, gemm_smem);
    const int attn_smem = (8448 + 4 * 2304) * 4;  // 70656
    cudaFuncSetAttribute(attn_kernel, cudaFuncAttributeMaxDynamicSharedMemorySize, attn_smem);

    wperm_kernel<<<(3 * NC * NC + 255) / 256, 256>>>(qkv_w, wq_p, 3 * NC);
    wperm_kernel<<<(NC * NC + 255) / 256, 256>>>(proj_w, wp_p, NC);
    gn_kernel<<<NB * NGROUPS, 256>>>(x, norm_w, norm_b);

    dim3 gq(NT / 128, (3 * NC) / 128, NB);
    mma_gemm_kernel<3 * NC, true, false><<<gq, 256, gemm_smem>>>(
        wq_p, xn_p, qkv_b, nullptr, qkv_p);

    dim3 ga(NT / 128, NB * NHEADS);
    attn_kernel<<<ga, 128, attn_smem>>>();

    dim3 gp(NT / 128, NC / 128, NB);
    mma_gemm_kernel<NC, false, true><<<gp, 256, gemm_smem>>>(
        wp_p, attn_p, proj_b, x, out);
}